// round 13
// baseline (speedup 1.0000x reference)
#include <cuda_runtime.h>
#include <cuda_fp16.h>
#include <cstdint>

// SeqClassLSTM via mma.sync fp16 (sm_103-portable).
// R11: (1) occupancy 3->4 CTAs/SM: rb-block processed as OUTER loop so only
// half the A-fragments/accumulators/h-outputs are live at once (regs 153->
// <=128); Btab fragments reloaded per rb (L1 has headroom). (2) i/f/o rows
// of W_hh/bias/W_ih prescaled by 0.5 (exact) so the MMA emits tanh's argument
// v/2 directly — removes 3 hmul2 per epilogue unit.
// Structure from R10: 32 seqs/warp, single-fp16 W_hh, tanh.approx.f16x2
// activations (c stays fp32), gate order n=gate*32+hid (gates of a (seq,hid)
// in one thread), h via stmatrix/ldmatrix, per-warp double buffer, only
// __syncwarp per step.

using u32 = uint32_t;

constexpr int T = 128;
constexpr int WARPS = 4;
constexpr int SEQ_CTA = 128;   // 32 per warp

__device__ __forceinline__ u32 sm_addr(const void* p) {
    u32 a;
    asm("{ .reg .u64 t; cvta.to.shared.u64 t, %1; cvt.u32.u64 %0, t; }" : "=r"(a) : "l"(p));
    return a;
}
// pack two f32 -> half2 (u32); LOW half = first arg
__device__ __forceinline__ u32 packh(float lo, float hi) {
    __half2 t = __floats2half2_rn(lo, hi);
    return *reinterpret_cast<u32*>(&t);
}
__device__ __forceinline__ __half2 asH2(u32 v) { return *reinterpret_cast<__half2*>(&v); }
__device__ __forceinline__ u32 asU(__half2 v) { return *reinterpret_cast<u32*>(&v); }
__device__ __forceinline__ __half2 tanh_h2(__half2 v) {
    u32 r, a = asU(v);
    asm("tanh.approx.f16x2 %0, %1;" : "=r"(r) : "r"(a));
    return asH2(r);
}

__device__ __forceinline__ void ldm4(u32 r[4], u32 a) {
    asm volatile("ldmatrix.sync.aligned.m8n8.x4.shared.b16 {%0,%1,%2,%3}, [%4];"
                 : "=r"(r[0]), "=r"(r[1]), "=r"(r[2]), "=r"(r[3]) : "r"(a));
}
__device__ __forceinline__ void ldm2(u32 r[2], u32 a) {
    asm volatile("ldmatrix.sync.aligned.m8n8.x2.shared.b16 {%0,%1}, [%2];"
                 : "=r"(r[0]), "=r"(r[1]) : "r"(a));
}
__device__ __forceinline__ void stm4(u32 a, u32 r0, u32 r1, u32 r2, u32 r3) {
    asm volatile("stmatrix.sync.aligned.m8n8.x4.shared.b16 [%0], {%1,%2,%3,%4};"
                 :: "r"(a), "r"(r0), "r"(r1), "r"(r2), "r"(r3) : "memory");
}
__device__ __forceinline__ void lds128(u32 r[4], u32 a) {
    asm volatile("ld.shared.v4.b32 {%0,%1,%2,%3}, [%4];"
                 : "=r"(r[0]), "=r"(r[1]), "=r"(r[2]), "=r"(r[3]) : "r"(a));
}
__device__ __forceinline__ u32 lds32(u32 a) {
    u32 r;
    asm volatile("ld.shared.u32 %0, [%1];" : "=r"(r) : "r"(a));
    return r;
}
__device__ __forceinline__ void sts128(u32 a, u32 r0, u32 r1, u32 r2, u32 r3) {
    asm volatile("st.shared.v4.b32 [%0], {%1,%2,%3,%4};"
                 :: "r"(a), "r"(r0), "r"(r1), "r"(r2), "r"(r3) : "memory");
}
__device__ __forceinline__ void mma16816(float d[4], const u32 a[4], u32 b0, u32 b1) {
    asm volatile("mma.sync.aligned.m16n8k16.row.col.f32.f16.f16.f32 "
                 "{%0,%1,%2,%3}, {%4,%5,%6,%7}, {%8,%9}, {%0,%1,%2,%3};"
                 : "+f"(d[0]), "+f"(d[1]), "+f"(d[2]), "+f"(d[3])
                 : "r"(a[0]), "r"(a[1]), "r"(a[2]), "r"(a[3]), "r"(b0), "r"(b1));
}
__device__ __forceinline__ void mma1688(float d[4], const u32 a[2], u32 b0) {
    asm volatile("mma.sync.aligned.m16n8k8.row.col.f32.f16.f16.f32 "
                 "{%0,%1,%2,%3}, {%4,%5}, {%6}, {%0,%1,%2,%3};"
                 : "+f"(d[0]), "+f"(d[1]), "+f"(d[2]), "+f"(d[3])
                 : "r"(a[0]), "r"(a[1]), "r"(b0));
}

__global__ void __launch_bounds__(128, 4)
lstm_hmma(const float* __restrict__ x,
          const float* __restrict__ W_ih,
          const float* __restrict__ W_hh,
          const float* __restrict__ b_ih,
          const float* __restrict__ b_hh,
          const float* __restrict__ W_fc,
          const float* __restrict__ b_fc,
          float* __restrict__ out,
          int B)
{
    // Btab[tau*32 + lane][4]: W fragments (i/f/o rows prescaled by 0.5). 8KB.
    __shared__ u32 Btab[16 * 32 * 4];
    __shared__ u32 bxs[16 * 32];                       // k8 bias/x B-frags, 2KB
    // Per-warp A buffers: 2 rb-blocks x 1KB, double-buffered. 16KB.
    __shared__ __align__(16) u32 hbuf[WARPS][2][512];
    __shared__ __align__(16) u32 xtile[WARPS][128];    // 32 rows x 16B
    __shared__ float wfc_s[64];
    __shared__ float bfc_s[2];

    const int tid = threadIdx.x;
    const int wid = tid >> 5, lane = tid & 31;

    // ---- weight-fragment table; gate g (==2) unscaled, i/f/o scaled 0.5 ----
    for (int i = tid; i < 16 * 32 * 4; i += 128) {
        const int j   = i & 3;
        const int ln  = (i >> 2) & 31;
        const int tau = i >> 7;
        const int gate = tau >> 2;
        const float s = (gate == 2) ? 1.0f : 0.5f;
        const int n = tau * 8 + (ln >> 2);
        const int k = ((j >> 1) * 16) + ((j & 1) * 8) + 2 * (ln & 3);
        Btab[i] = packh(s * W_hh[n * 32 + k], s * W_hh[n * 32 + k + 1]);
    }
    // ---- k8 (bias/x) B fragments table (same 0.5 prescale on i/f/o) ----
    for (int i = tid; i < 16 * 32; i += 128) {
        const int ln = i & 31, tau = i >> 5;
        const int gate = tau >> 2;
        const float s = (gate == 2) ? 1.0f : 0.5f;
        const int sel = ln & 3;
        const int n = tau * 8 + (ln >> 2);
        const float bias = s * (b_ih[n] + b_hh[n]);
        const float wx = s * W_ih[n];
        const float bh = __half2float(__float2half_rn(bias));
        const float wh = __half2float(__float2half_rn(wx));
        u32 v;
        if (sel == 0)      v = packh(bh, bias - bh);      // k0=b_hi, k1=b_lo
        else if (sel == 1) v = packh(wh, wh);             // k2,k3 = wx_hi
        else if (sel == 2) v = packh(wx - wh, 0.0f);      // k4 = wx_lo
        else               v = 0u;
        bxs[i] = v;
    }

    for (int i = tid; i < WARPS * 2 * 512; i += 128) (&hbuf[0][0][0])[i] = 0;
    for (int i = tid; i < WARPS * 128; i += 128) (&xtile[0][0])[i] = 0;
    if (tid < 64) wfc_s[tid] = W_fc[tid];
    if (tid < 2) bfc_s[tid] = b_fc[tid];
    __syncthreads();

    const u32 hb0 = sm_addr(&hbuf[wid][0][0]);
    const u32 hb1 = sm_addr(&hbuf[wid][1][0]);
    const u32 xb  = sm_addr(&xtile[wid][0]);
    const u32 btb = sm_addr(Btab);
    const u32 bxb = sm_addr(bxs);
    const u32 lmo  = ((u32)(lane >> 3) * 128u) + ((u32)(lane & 7) * 16u);
    const u32 lmo2 = ((u32)((lane >> 3) & 1) * 128u) + ((u32)(lane & 7) * 16u);

    // each lane owns x-row = lane (seq within warp)
    const int seqr = blockIdx.x * SEQ_CTA + wid * 32 + lane;
    const bool sv = (seqr < B);

    float xn = sv ? __ldg(&x[(size_t)seqr * T]) : 0.0f;
    {
        const float xh = __half2float(__float2half_rn(xn));
        sts128(xb + (u32)lane * 16u, 0x3C003C00u, packh(xh, xn - xh), packh(xh, 0.0f), 0u);
    }
    __syncwarp();

    float cst[32];
#pragma unroll
    for (int i = 0; i < 32; ++i) cst[i] = 0.0f;

    const __half2 H05 = __floats2half2_rn(0.5f, 0.5f);

#pragma unroll 1
    for (int t = 0; t < T; ++t) {
        const u32 rbuf = (t & 1) ? hb1 : hb0;
        const u32 wbuf = (t & 1) ? hb0 : hb1;

        float xnext = (sv && (t + 1) < T) ? __ldg(&x[(size_t)seqr * T + t + 1]) : 0.0f;

        // rb OUTER: halves live registers (A frags, dd, hst per half)
#pragma unroll
        for (int rb = 0; rb < 2; ++rb) {
            u32 A0[4], A1[4], Ax[2];
            ldm4(A0, rbuf + (u32)rb * 1024u + lmo);
            ldm4(A1, rbuf + (u32)rb * 1024u + 512u + lmo);
            ldm2(Ax, xb + (u32)rb * 256u + lmo2);

            u32 hst[8];
#pragma unroll
            for (int q = 0; q < 4; ++q) {
                float dd[4][4];
#pragma unroll
                for (int gate = 0; gate < 4; ++gate) {
                    const int tau = q + gate * 4;
                    u32 bh[4];
                    lds128(bh, btb + (u32)(tau * 32 + lane) * 16u);
                    const u32 bxv = lds32(bxb + (u32)(tau * 32 + lane) * 4u);
                    float* d = dd[gate];
                    d[0] = 0.0f; d[1] = 0.0f; d[2] = 0.0f; d[3] = 0.0f;
                    mma16816(d, A0, bh[0], bh[1]);
                    mma16816(d, A1, bh[2], bh[3]);
                    mma1688(d, Ax, bxv);
                }
                // epilogue: dd for i/f/o is already v/2 (prescaled weights)
#pragma unroll
                for (int pr = 0; pr < 2; ++pr) {
                    const int e = 2 * pr;
                    const __half2 iv = asH2(packh(dd[0][e], dd[0][e + 1]));
                    const __half2 fv = asH2(packh(dd[1][e], dd[1][e + 1]));
                    const __half2 gv = asH2(packh(dd[2][e], dd[2][e + 1]));
                    const __half2 ov = asH2(packh(dd[3][e], dd[3][e + 1]));
                    const __half2 si = __hfma2(tanh_h2(iv), H05, H05);
                    const __half2 sf = __hfma2(tanh_h2(fv), H05, H05);
                    const __half2 tg = tanh_h2(gv);
                    const __half2 so = __hfma2(tanh_h2(ov), H05, H05);
                    const __half2 p = __hmul2(si, tg);
                    const int ci = (rb * 2 + pr) * 8 + q * 2;
                    const float cn0 = fmaf(__low2float(sf),  cst[ci],     __low2float(p));
                    const float cn1 = fmaf(__high2float(sf), cst[ci + 1], __high2float(p));
                    cst[ci] = cn0;
                    cst[ci + 1] = cn1;
                    const __half2 tc = tanh_h2(asH2(packh(cn0, cn1)));
                    hst[q * 2 + pr] = asU(__hmul2(so, tc));
                }
            }
            stm4(wbuf + (u32)rb * 1024u + lmo,
                 hst[0], hst[1], hst[2], hst[3]);
            stm4(wbuf + (u32)rb * 1024u + 512u + lmo,
                 hst[4], hst[5], hst[6], hst[7]);
        }
        {
            const float xh = __half2float(__float2half_rn(xnext));
            sts128(xb + (u32)lane * 16u, 0x3C003C00u, packh(xh, xnext - xh),
                   packh(xh, 0.0f), 0u);
        }
        __syncwarp();
    }

    // ---- FC from final h (hbuf parity 0; T even) ----
    const int a2 = 2 * (lane & 3);
    const int r0 = lane >> 2;
#pragma unroll
    for (int rb = 0; rb < 2; ++rb) {
        float acc[2][2] = {{0.0f, 0.0f}, {0.0f, 0.0f}};
#pragma unroll
        for (int q = 0; q < 4; ++q) {
#pragma unroll
            for (int e = 0; e < 2; ++e) {
                const int hid = 8 * q + a2 + e;
                const int chunk = hid >> 4;
                const int kk = hid & 15;
                const int khalf = kk >> 3;
                const int col = kk & 7;
                const float f0 = wfc_s[hid];
                const float f1 = wfc_s[32 + hid];
#pragma unroll
                for (int rg = 0; rg < 2; ++rg) {
                    const u32 ahi = hb0 + (u32)rb * 1024u
                                  + (u32)(chunk * 4 + khalf * 2 + rg) * 128u
                                  + (u32)r0 * 16u + (u32)col * 2u;
                    u32 hv16;
                    asm volatile("ld.shared.u16 %0, [%1];" : "=r"(hv16) : "r"(ahi));
                    const float h = __half2float(*reinterpret_cast<__half*>(&hv16));
                    acc[rg][0] = fmaf(h, f0, acc[rg][0]);
                    acc[rg][1] = fmaf(h, f1, acc[rg][1]);
                }
            }
        }
#pragma unroll
        for (int rg = 0; rg < 2; ++rg)
#pragma unroll
            for (int o = 0; o < 2; ++o) {
                acc[rg][o] += __shfl_xor_sync(0xffffffffu, acc[rg][o], 1);
                acc[rg][o] += __shfl_xor_sync(0xffffffffu, acc[rg][o], 2);
            }
        if ((lane & 3) == 0) {
            const int s0 = blockIdx.x * SEQ_CTA + wid * 32 + rb * 16 + r0;
            if (s0 < B) {
                out[(size_t)s0 * 2 + 0] = acc[0][0] + bfc_s[0];
                out[(size_t)s0 * 2 + 1] = acc[0][1] + bfc_s[1];
            }
            const int s1 = s0 + 8;
            if (s1 < B) {
                out[(size_t)s1 * 2 + 0] = acc[1][0] + bfc_s[0];
                out[(size_t)s1 * 2 + 1] = acc[1][1] + bfc_s[1];
            }
        }
    }
}

extern "C" void kernel_launch(void* const* d_in, const int* in_sizes, int n_in,
                              void* d_out, int out_size)
{
    const float* x    = (const float*)d_in[0];
    const float* W_ih = (const float*)d_in[1];
    const float* W_hh = (const float*)d_in[2];
    const float* b_ih = (const float*)d_in[3];
    const float* b_hh = (const float*)d_in[4];
    const float* W_fc = (const float*)d_in[5];
    const float* b_fc = (const float*)d_in[6];
    float* out = (float*)d_out;

    const int B = in_sizes[0] / T;                // x has B*T elements
    const int blocks = (B + SEQ_CTA - 1) / SEQ_CTA;

    lstm_hmma<<<blocks, 128>>>(x, W_ih, W_hh, b_ih, b_hh, W_fc, b_fc, out, B);
}